// round 3
// baseline (speedup 1.0000x reference)
#include <cuda_runtime.h>
#include <math.h>

// TransformationRotationLoss — single fused streaming reduction.
// loss[j] = mean_over_masked_rows( ALPHA*u_ta[j]^2 + BETTA*u_tb[j]^2 )
// Identities used:
//   c = n1·u2,  p = v2 - n1(n1·v2) = |v2| sin(a) n2,  q = p/|v2| = sin(a) n2
//   u_ta = sin(a)(n2 s1 - n1 s2) = q*s1 - n1*Σq
//   u_tb = (c-1)(n1 s1 + n2 s2) = (c-1) n1 s1 - q*Σq/(1+c)

#define ALPHA 0.7f
#define BETTA 0.3f

static constexpr int THREADS    = 256;
static constexpr int MAX_BLOCKS = 4096;

__device__ float4 g_partials[MAX_BLOCKS];
__device__ unsigned int g_ticket = 0;

__device__ __forceinline__ void process_row(
    float ax, float ay, float az,
    float bx, float by, float bz,
    float& sx, float& sy, float& sz, float& cnt)
{
    float r1sq = fmaf(ax, ax, fmaf(ay, ay, az * az));
    if (!(r1sq > 1e-16f)) return;   // mask: ||v1|| > 1e-8
    float r2sq = fmaf(bx, bx, fmaf(by, by, bz * bz));
    float d12  = fmaf(ax, bx, fmaf(ay, by, az * bz));

    float inv1 = rsqrtf(r1sq);
    float inv2 = (r2sq > 0.0f) ? rsqrtf(r2sq) : 1.0f;

    float n1x = ax * inv1, n1y = ay * inv1, n1z = az * inv1;

    float proj = d12 * inv1;               // n1·v2
    float c = proj * inv2;                 // cos(angle)
    c = fminf(1.0f, fmaxf(-1.0f, c));

    // q = (v2 - n1*proj) * inv2 = sin(a) * n2
    float qx = fmaf(-n1x, proj, bx) * inv2;
    float qy = fmaf(-n1y, proj, by) * inv2;
    float qz = fmaf(-n1z, proj, bz) * inv2;

    float s1 = n1x + n1y + n1z;
    float sq = qx + qy + qz;

    // u_ta = q*s1 - n1*sq
    float tax = fmaf(qx, s1, -n1x * sq);
    float tay = fmaf(qy, s1, -n1y * sq);
    float taz = fmaf(qz, s1, -n1z * sq);

    // u_tb = (c-1)*s1*n1 - (sq/(1+c))*q
    float w1 = (c - 1.0f) * s1;
    float w2 = sq * __frcp_rn(fmaxf(1.0f + c, 1e-12f));
    float tbx = fmaf(n1x, w1, -qx * w2);
    float tby = fmaf(n1y, w1, -qy * w2);
    float tbz = fmaf(n1z, w1, -qz * w2);

    sx += fmaf(ALPHA, tax * tax, BETTA * tbx * tbx);
    sy += fmaf(ALPHA, tay * tay, BETTA * tby * tby);
    sz += fmaf(ALPHA, taz * taz, BETTA * tbz * tbz);
    cnt += 1.0f;
}

// Block-reduce (sx,sy,sz,cnt) into shared `result`; valid after return.
__device__ __forceinline__ void block_reduce(
    float sx, float sy, float sz, float cnt, float4* result)
{
    #pragma unroll
    for (int o = 16; o > 0; o >>= 1) {
        sx  += __shfl_down_sync(0xffffffffu, sx,  o);
        sy  += __shfl_down_sync(0xffffffffu, sy,  o);
        sz  += __shfl_down_sync(0xffffffffu, sz,  o);
        cnt += __shfl_down_sync(0xffffffffu, cnt, o);
    }
    __shared__ float4 smem[THREADS / 32];
    int lane = threadIdx.x & 31;
    int warp = threadIdx.x >> 5;
    if (lane == 0) smem[warp] = make_float4(sx, sy, sz, cnt);
    __syncthreads();
    if (warp == 0) {
        float4 v = (lane < (blockDim.x >> 5)) ? smem[lane]
                                              : make_float4(0.f, 0.f, 0.f, 0.f);
        sx = v.x; sy = v.y; sz = v.z; cnt = v.w;
        #pragma unroll
        for (int o = 16; o > 0; o >>= 1) {
            sx  += __shfl_down_sync(0xffffffffu, sx,  o);
            sy  += __shfl_down_sync(0xffffffffu, sy,  o);
            sz  += __shfl_down_sync(0xffffffffu, sz,  o);
            cnt += __shfl_down_sync(0xffffffffu, cnt, o);
        }
        if (lane == 0) *result = make_float4(sx, sy, sz, cnt);
    }
    __syncthreads();
}

__device__ __forceinline__ float fix_num(float x) {
    if (isnan(x)) return 0.0f;
    if (isinf(x)) return x > 0.0f ? 0.1f : -0.1f;
    return x;
}

__global__ __launch_bounds__(THREADS, 6)
void trl_fused_kernel(const float* __restrict__ v1,
                      const float* __restrict__ v2,
                      float* __restrict__ out,
                      int rows)
{
    float sx = 0.f, sy = 0.f, sz = 0.f, cnt = 0.f;

    const int tid   = blockIdx.x * blockDim.x + threadIdx.x;
    const int total = gridDim.x * blockDim.x;
    const int rows4 = rows >> 2;   // groups of 4 rows = 3 float4 per input

    const float4* __restrict__ a4 = reinterpret_cast<const float4*>(v1);
    const float4* __restrict__ b4 = reinterpret_cast<const float4*>(v2);

    // Exactly one group per thread (grid sized to cover rows4):
    // 6 independent LDG.128 front-batched.
    if (tid < rows4) {
        float4 a0 = a4[3 * tid + 0];
        float4 a1 = a4[3 * tid + 1];
        float4 a2 = a4[3 * tid + 2];
        float4 b0 = b4[3 * tid + 0];
        float4 b1 = b4[3 * tid + 1];
        float4 b2 = b4[3 * tid + 2];

        process_row(a0.x, a0.y, a0.z, b0.x, b0.y, b0.z, sx, sy, sz, cnt);
        process_row(a0.w, a1.x, a1.y, b0.w, b1.x, b1.y, sx, sy, sz, cnt);
        process_row(a1.z, a1.w, a2.x, b1.z, b1.w, b2.x, sx, sy, sz, cnt);
        process_row(a2.y, a2.z, a2.w, b2.y, b2.z, b2.w, sx, sy, sz, cnt);
    }
    // Tail rows (rows % 4), scalar — empty when rows % 4 == 0.
    for (int r = (rows4 << 2) + tid; r < rows; r += total) {
        process_row(v1[3 * r], v1[3 * r + 1], v1[3 * r + 2],
                    v2[3 * r], v2[3 * r + 1], v2[3 * r + 2],
                    sx, sy, sz, cnt);
    }

    __shared__ float4 result;
    block_reduce(sx, sy, sz, cnt, &result);

    // Publish partial; last block to arrive finalizes.
    __shared__ bool is_last;
    if (threadIdx.x == 0) {
        g_partials[blockIdx.x] = result;
        __threadfence();
        unsigned int t = atomicAdd(&g_ticket, 1u);
        is_last = (t == gridDim.x - 1);
    }
    __syncthreads();

    if (is_last) {
        float fx = 0.f, fy = 0.f, fz = 0.f, fc = 0.f;
        for (int i = threadIdx.x; i < (int)gridDim.x; i += blockDim.x) {
            float4 p;
            const float4* src = &g_partials[i];
            asm volatile("ld.global.cg.v4.f32 {%0,%1,%2,%3}, [%4];"
                         : "=f"(p.x), "=f"(p.y), "=f"(p.z), "=f"(p.w)
                         : "l"(src));
            fx += p.x; fy += p.y; fz += p.z; fc += p.w;
        }
        __shared__ float4 final_r;
        block_reduce(fx, fy, fz, fc, &final_r);
        if (threadIdx.x == 0) {
            float inv = 1.0f / fmaxf(final_r.w, 1.0f);
            out[0] = fix_num(final_r.x * inv);
            out[1] = fix_num(final_r.y * inv);
            out[2] = fix_num(final_r.z * inv);
            g_ticket = 0;   // reset for graph replay
        }
    }
}

extern "C" void kernel_launch(void* const* d_in, const int* in_sizes, int n_in,
                              void* d_out, int out_size)
{
    const float* v1 = (const float*)d_in[0];
    const float* v2 = (const float*)d_in[1];
    float* out = (float*)d_out;

    int rows  = in_sizes[0] / 3;
    int rows4 = rows >> 2;
    int blocks = (rows4 + THREADS - 1) / THREADS;   // one group per thread
    if (blocks < 1) blocks = 1;
    if (blocks > MAX_BLOCKS) blocks = MAX_BLOCKS;

    trl_fused_kernel<<<blocks, THREADS>>>(v1, v2, out, rows);
}